// round 1
// baseline (speedup 1.0000x reference)
#include <cuda_runtime.h>
#include <cuda_bf16.h>

#define BB 8
#define QQ 2048
#define GG 128
#define CC 512

// Scratch: transposed cost [B][G][Q] for coalesced solver row reads (8 MB).
__device__ float g_costT[BB * GG * QQ];
// 1 if int-typed inputs are int64, 0 if int32.
__device__ int g_i64;

// ---------------------------------------------------------------------------
// Detect whether label/nactual buffers are int64 or int32.
// Reads only the first 512 int64 words = 4096 bytes, which fits inside the
// buffer under either interpretation (int32: 1024*4 = 4096 B exactly).
// Genuine int64 labels are all in [0,512). If the data is really int32 pairs,
// the packed int64 view combines two labels -> value >= 2^32 w.h.p.
// ---------------------------------------------------------------------------
__global__ void detect_kernel(const long long* __restrict__ lab) {
    if (blockIdx.x == 0 && threadIdx.x == 0) {
        int i64 = 1;
        for (int i = 0; i < 512; ++i) {
            long long v = lab[i];
            if (v < 0 || v >= 512) { i64 = 0; break; }
        }
        g_i64 = i64;
    }
}

// ---------------------------------------------------------------------------
// final_cost[b,q,g] = 2*classdiff + 5*center + 1*size - 2*gious
// classdiff uses the focal-loss pos/neg terms at c = label[b,g].
// ---------------------------------------------------------------------------
__global__ void cost_kernel(const float* __restrict__ sem,
                            const float* __restrict__ cen,
                            const float* __restrict__ siz,
                            const float* __restrict__ gio,
                            const void*  __restrict__ labels,
                            float* __restrict__ outCost) {
    int idx = blockIdx.x * blockDim.x + threadIdx.x;
    if (idx >= BB * QQ * GG) return;
    int g  = idx & (GG - 1);
    int bq = idx >> 7;             // b*Q + q
    int b  = bq >> 11;
    int li = (b << 7) + g;

    int lab;
    if (g_i64) lab = (int)((const long long*)labels)[li];
    else       lab = ((const int*)labels)[li];
    lab &= (CC - 1);               // defensive clamp (no-op for valid data)

    float x = sem[((long long)bq << 9) + lab];
    float p = 1.0f / (1.0f + expf(-x));
    float om = 1.0f - p;
    float pos = 0.25f * om * om * (-logf(p + 1e-8f));
    float neg = 0.75f * p * p * (-log1pf(-(p - 1e-8f)));
    outCost[idx] = 2.0f * (pos - neg) + 5.0f * cen[idx] + siz[idx] - 2.0f * gio[idx];
}

// ---------------------------------------------------------------------------
// Tiled transpose: cost [b][q][g] (stride G) -> costT [b][g][q] (stride Q).
// ---------------------------------------------------------------------------
__global__ void transpose_kernel(const float* __restrict__ src) {
    __shared__ float tile[32][33];
    int b  = blockIdx.z;
    int q0 = blockIdx.x * 32;
    int g0 = blockIdx.y * 32;
    const float* s = src + (long long)b * QQ * GG;
    float* d = g_costT + (long long)b * QQ * GG;
    #pragma unroll
    for (int r = threadIdx.y; r < 32; r += 8)
        tile[r][threadIdx.x] = s[(q0 + r) * GG + g0 + threadIdx.x];
    __syncthreads();
    #pragma unroll
    for (int r = threadIdx.y; r < 32; r += 8)
        d[(g0 + r) * QQ + q0 + threadIdx.x] = tile[threadIdx.x][r];
}

// ---------------------------------------------------------------------------
// Exact replica of the reference _lsa (including its quirk: minv/way are
// per-iteration copies that never persist, so each inner iteration recomputes
// slacks from the current chain row only, and assignment is simply
// p[final_free_col] = i). Duals u/v DO persist across rows. float64 math,
// numpy first-index tie-break on the argmin.
// One CTA per batch; 256 threads scan the 2048 columns.
// ---------------------------------------------------------------------------
__global__ void lsa_kernel(const void* __restrict__ nactual,
                           void* __restrict__ outInds,
                           float* __restrict__ outMask,
                           int rawMode) {
    int b = blockIdx.x;
    int t = threadIdx.x;

    __shared__ double v[QQ + 1];
    __shared__ double u[GG + 1];
    __shared__ unsigned short p_[QQ + 1];
    __shared__ unsigned char used_[QQ + 1];
    __shared__ unsigned short listCol[GG + 2];
    __shared__ unsigned short listRow[GG + 2];
    __shared__ int s_nlist;
    __shared__ int s_j0, s_i0, s_done;
    __shared__ double red_val[8];
    __shared__ int    red_idx[8];

    int n;
    if (g_i64) n = (int)((const long long*)nactual)[b];
    else       n = ((const int*)nactual)[b];
    if (n < 0) n = 0;
    if (n > GG) n = GG;

    const float* CT = g_costT + (long long)b * GG * QQ;

    for (int j = t; j <= QQ; j += 256) { v[j] = 0.0; p_[j] = 0; used_[j] = 0; }
    for (int ii = t; ii <= GG; ii += 256) u[ii] = 0.0;
    __syncthreads();

    for (int i = 1; i <= n; ++i) {
        if (t == 0) { p_[0] = (unsigned short)i; s_j0 = 0; s_nlist = 0; }
        // (no barrier needed: only t0 reads s_j0/p_[0] before the next barrier)
        while (true) {
            if (t == 0) {
                int j0 = s_j0;
                used_[j0] = 1;
                int r = p_[j0];
                listCol[s_nlist] = (unsigned short)j0;
                listRow[s_nlist] = (unsigned short)r;
                s_nlist++;
                s_i0 = r;
            }
            __syncthreads();

            int i0 = s_i0;
            double ui = u[i0];
            const float* row = CT + (i0 - 1) * QQ;

            double best = 1e300;
            int bestj = QQ + 1;
            #pragma unroll
            for (int k = 0; k < 8; ++k) {
                int j = 1 + t + (k << 8);        // 1..2048, coalesced across threads
                if (!used_[j]) {
                    double cur = (double)row[j - 1] - ui - v[j];
                    if (cur < best || (cur == best && j < bestj)) { best = cur; bestj = j; }
                }
            }
            // warp reduce (value, first-index tie-break)
            #pragma unroll
            for (int off = 16; off; off >>= 1) {
                double ov = __shfl_down_sync(0xffffffffu, best, off);
                int    oj = __shfl_down_sync(0xffffffffu, bestj, off);
                if (ov < best || (ov == best && oj < bestj)) { best = ov; bestj = oj; }
            }
            if ((t & 31) == 0) { red_val[t >> 5] = best; red_idx[t >> 5] = bestj; }
            __syncthreads();

            if (t == 0) {
                double bv = red_val[0]; int bj = red_idx[0];
                #pragma unroll
                for (int w = 1; w < 8; ++w) {
                    double wv = red_val[w]; int wj = red_idx[w];
                    if (wv < bv || (wv == bv && wj < bj)) { bv = wv; bj = wj; }
                }
                // dual updates over all used columns of this row's chain
                int nl = s_nlist;
                for (int e = 0; e < nl; ++e) {
                    u[listRow[e]] += bv;
                    v[listCol[e]] -= bv;
                }
                int done = (p_[bj] == 0);
                if (done) {
                    p_[bj] = (unsigned short)i;       // reference: p[j0] = p[way[j0]=0] = i
                    for (int e = 0; e < nl; ++e) used_[listCol[e]] = 0;  // fresh per row
                } else {
                    s_j0 = bj;
                }
                s_done = done;
            }
            __syncthreads();
            if (s_done) break;
        }
    }

    // Outputs: column j assigned to row p_[j] -> proposal j-1 matched to gt p_[j]-1.
    for (int j = t; j < QQ; j += 256) {
        int pi = p_[j + 1];
        int off = b * QQ + j;
        float mv = pi > 0 ? 1.0f : 0.0f;
        long long gi = pi > 0 ? (long long)(pi - 1) : 0;
        if (rawMode) ((long long*)outInds)[off] = gi;
        else         ((float*)outInds)[off] = (float)gi;
        outMask[off] = mv;
    }
}

extern "C" void kernel_launch(void* const* d_in, const int* in_sizes, int n_in,
                              void* d_out, int out_size) {
    const float* sem = (const float*)d_in[0];
    const float* cen = (const float*)d_in[1];
    const float* siz = (const float*)d_in[2];
    const float* gio = (const float*)d_in[3];
    const void*  lab = d_in[4];
    const void*  na  = d_in[5];

    // Output layout:
    //  - 2129920 elems: everything cast to the output dtype and concatenated
    //    [inds(16384), mask(16384), cost(2097152)] -> treat as float32.
    //  - 2146304 elems: raw-byte concat viewed as f32 elements:
    //    int64 inds (131072 B) | f32 mask (65536 B) | f32 cost (8388608 B).
    int rawMode = (out_size == 2146304) ? 1 : 0;
    void*  outInds;
    float* outMask;
    float* outCost;
    if (rawMode) {
        outInds = d_out;
        outMask = (float*)((char*)d_out + (size_t)BB * QQ * 8);
        outCost = (float*)((char*)d_out + (size_t)BB * QQ * 8 + (size_t)BB * QQ * 4);
    } else {
        outInds = d_out;
        outMask = (float*)d_out + BB * QQ;
        outCost = (float*)d_out + 2 * BB * QQ;
    }

    detect_kernel<<<1, 1>>>((const long long*)lab);
    cost_kernel<<<(BB * QQ * GG) / 256, 256>>>(sem, cen, siz, gio, lab, outCost);
    transpose_kernel<<<dim3(QQ / 32, GG / 32, BB), dim3(32, 8)>>>(outCost);
    lsa_kernel<<<BB, 256>>>(na, outInds, outMask, rawMode);
}

// round 2
// speedup vs baseline: 2.1429x; 2.1429x over previous
#include <cuda_runtime.h>
#include <cuda_bf16.h>

#define BB 8
#define QQ 2048
#define GG 128
#define CC 512
#define KCAND 144

// ---------------- global scratch (no allocs allowed) ----------------
__device__ float g_costT[BB * GG * QQ];                    // [b][g][q]  8MB
__device__ unsigned long long g_cand[BB * GG * KCAND];     // sorted (val,idx) per row
__device__ int g_lab[BB * GG];
__device__ int g_n[BB];

// ---------------------------------------------------------------------------
// Prep: detect int64 vs int32 for labels/nactual, convert to int32 scratch.
// Reading 512 int64 = 4096B fits the buffer under either interpretation.
// ---------------------------------------------------------------------------
__global__ void prep_kernel(const void* __restrict__ lab, const void* __restrict__ na) {
    __shared__ int s_bad;
    int t = threadIdx.x;
    if (t == 0) s_bad = 0;
    __syncthreads();
    if (t < 512) {
        long long v = ((const long long*)lab)[t];
        if (v < 0 || v >= CC) s_bad = 1;   // benign race, same value
    }
    __syncthreads();
    if (s_bad == 0) {
        if (t < BB * GG) g_lab[t] = (int)((const long long*)lab)[t];
        if (t < BB)      g_n[t]   = (int)((const long long*)na)[t];
    } else {
        if (t < BB * GG) g_lab[t] = ((const int*)lab)[t];
        if (t < BB)      g_n[t]   = ((const int*)na)[t];
    }
}

// ---------------------------------------------------------------------------
// Cost: final_cost[b,q,g] = 2*(pos-neg) + 5*center + size - 2*gious
// 4 consecutive g per thread (float4 streams + 4 sem gathers).
// ---------------------------------------------------------------------------
__global__ void cost_kernel(const float* __restrict__ sem,
                            const float* __restrict__ cen,
                            const float* __restrict__ siz,
                            const float* __restrict__ gio,
                            float* __restrict__ outCost) {
    int tid  = blockIdx.x * blockDim.x + threadIdx.x;
    int base = tid << 2;
    if (base >= BB * QQ * GG) return;
    int g  = base & (GG - 1);
    int bq = base >> 7;
    int b  = bq >> 11;

    float4 c4 = *(const float4*)(cen + base);
    float4 s4 = *(const float4*)(siz + base);
    float4 i4 = *(const float4*)(gio + base);
    const float* semRow = sem + ((long long)bq << 9);

    float cls[4];
    #pragma unroll
    for (int k = 0; k < 4; ++k) {
        int lb = g_lab[(b << 7) + g + k] & (CC - 1);
        float x = __ldg(semRow + lb);
        float p = 1.0f / (1.0f + expf(-x));
        float om = 1.0f - p;
        float pos = 0.25f * om * om * (-logf(p + 1e-8f));
        float neg = 0.75f * p * p * (-log1pf(-(p - 1e-8f)));
        cls[k] = pos - neg;
    }
    float4 o;
    o.x = 2.0f * cls[0] + 5.0f * c4.x + s4.x - 2.0f * i4.x;
    o.y = 2.0f * cls[1] + 5.0f * c4.y + s4.y - 2.0f * i4.y;
    o.z = 2.0f * cls[2] + 5.0f * c4.z + s4.z - 2.0f * i4.z;
    o.w = 2.0f * cls[3] + 5.0f * c4.w + s4.w - 2.0f * i4.w;
    *(float4*)(outCost + base) = o;
}

// ---------------------------------------------------------------------------
// Transpose [b][q][g] -> [b][g][q]
// ---------------------------------------------------------------------------
__global__ void transpose_kernel(const float* __restrict__ src) {
    __shared__ float tile[32][33];
    int b  = blockIdx.z;
    int q0 = blockIdx.x * 32;
    int g0 = blockIdx.y * 32;
    const float* s = src + (long long)b * QQ * GG;
    float* d = g_costT + (long long)b * QQ * GG;
    #pragma unroll
    for (int r = threadIdx.y; r < 32; r += 8)
        tile[r][threadIdx.x] = s[(q0 + r) * GG + g0 + threadIdx.x];
    __syncthreads();
    #pragma unroll
    for (int r = threadIdx.y; r < 32; r += 8)
        d[(g0 + r) * QQ + q0 + threadIdx.x] = tile[threadIdx.x][r];
}

// ---------------------------------------------------------------------------
// Per-row bitonic sort of packed (sortable_f32 << 32 | (j+1)) u64 keys.
// Ascending u64 order == ascending (value, index) == numpy strict-< argmin order.
// Writes top-KCAND candidates per row.
// ---------------------------------------------------------------------------
__global__ void sort_kernel() {
    __shared__ unsigned long long key[QQ];
    int t = threadIdx.x;
    long long rowid = blockIdx.x;                 // b*128+g
    const float* row = g_costT + rowid * QQ;
    #pragma unroll
    for (int i = 0; i < 8; ++i) {
        int j = t + (i << 8);
        unsigned bits = __float_as_uint(row[j]);
        unsigned s = (bits & 0x80000000u) ? ~bits : (bits | 0x80000000u);
        key[j] = ((unsigned long long)s << 32) | (unsigned)(j + 1);
    }
    __syncthreads();
    for (int k = 2; k <= QQ; k <<= 1) {
        for (int j = k >> 1; j > 0; j >>= 1) {
            #pragma unroll 4
            for (int i = 0; i < 8; ++i) {
                int idx = t + (i << 8);
                int partner = idx ^ j;
                if (partner > idx) {
                    unsigned long long a = key[idx], c = key[partner];
                    bool up = ((idx & k) == 0);
                    if ((a > c) == up) { key[idx] = c; key[partner] = a; }
                }
            }
            __syncthreads();
        }
    }
    if (t < KCAND) g_cand[rowid * KCAND + t] = key[t];
}

// ---------------------------------------------------------------------------
// Solver. Exact reference semantics:
//   per inner iter: delta = min over free j of fl(fl(row[i0][j]-u[i0]) - v[j]),
//   strict-< first-index tie-break; duals over chain; assign p[freecol]=i.
// Split: v==0 exactly on unassigned cols -> part A = first unassigned in
// presorted candidates (exact order); part B = <=128 assigned cols in f64 from
// a shared cache. Dual updates applied in parallel next phase (pending set
// excludes i0's row; B skips chain cols via used_, so no races).
// ---------------------------------------------------------------------------
struct LsaSmem {
    double v[QQ + 1];
    double u[GG + 2];
    double bval[4];
    double s_delta;
    unsigned long long aPacked;
    unsigned long long cand[GG][32];
    float asgVals[GG][GG + 1];        // [slot][row], stride 129 -> conflict-free
    int bidx[4];
    int s_i0, s_done, s_nlist, s_dualCnt, s_asgCnt, s_gatherCol, s_gatherSlot;
    unsigned short p_[QQ + 1];
    unsigned short asgColArr[GG + 4];
    unsigned short chainCol[GG + 4];
    unsigned short chainRow[GG + 4];
    unsigned char used_[QQ + 1];
};

__global__ void lsa_kernel(void* __restrict__ outInds, float* __restrict__ outMask,
                           const float* __restrict__ outCost, int rawMode) {
    extern __shared__ char smemRaw[];
    LsaSmem* S = (LsaSmem*)smemRaw;
    int b = blockIdx.x, t = threadIdx.x;
    int warp = t >> 5, lane = t & 31;
    int n = g_n[b]; if (n < 0) n = 0; if (n > GG) n = GG;
    const float* costB = outCost + (long long)b * QQ * GG;

    for (int j = t; j <= QQ; j += 256) { S->v[j] = 0.0; S->p_[j] = 0; S->used_[j] = 0; }
    for (int j = t; j < GG + 2; j += 256) S->u[j] = 0.0;
    #pragma unroll
    for (int i = 0; i < 16; ++i) {
        int idx = t + (i << 8);
        int r = idx >> 5, k = idx & 31;
        S->cand[r][k] = g_cand[(long long)(b * GG + r) * KCAND + k];
    }
    if (t == 0) { S->s_asgCnt = 0; S->s_gatherCol = -1; S->s_dualCnt = 0; }
    __syncthreads();

    for (int i = 1; i <= n; ++i) {
        // ---- outer phase 1: flush prev row's pending duals + used, gather new col
        {
            int dc = S->s_dualCnt;
            if (t < dc) {
                double d = S->s_delta;
                S->u[S->chainRow[t]] += d;
                S->v[S->chainCol[t]] -= d;
                S->used_[S->chainCol[t]] = 0;
            }
            int gc = S->s_gatherCol;
            if (gc > 0 && t < GG)
                S->asgVals[S->s_gatherSlot][t] = costB[(long long)(gc - 1) * GG + t];
            if (t == 0) { S->chainCol[0] = 0; S->chainRow[0] = (unsigned short)i; S->used_[0] = 1; }
        }
        __syncthreads();
        if (t == 0) { S->s_i0 = i; S->s_done = 0; S->s_nlist = 1; S->s_dualCnt = 0; }

        for (;;) {
            __syncthreads();                     // barA: t0 state + pendings visible
            if (S->s_done) break;
            int i0 = S->s_i0;
            // pending duals from prev collision iter (set excludes row i0 / B-read cols)
            {
                int dc = S->s_dualCnt;
                if (t < dc) {
                    double d = S->s_delta;
                    S->u[S->chainRow[t]] += d;
                    S->v[S->chainCol[t]] -= d;
                }
            }
            if (t < GG) {
                // ---- part B: assigned columns, exact f64
                double myv = 1e300; int myj = 1 << 30;
                int cnt = S->s_asgCnt;
                if (t < cnt) {
                    int jb = S->asgColArr[t];
                    if (!S->used_[jb]) {
                        double ui = S->u[i0];
                        double cur = ((double)S->asgVals[t][i0 - 1] - ui) - S->v[jb];
                        myv = cur; myj = jb;
                    }
                }
                #pragma unroll
                for (int off = 16; off; off >>= 1) {
                    double ov = __shfl_down_sync(0xffffffffu, myv, off);
                    int    oj = __shfl_down_sync(0xffffffffu, myj, off);
                    if (ov < myv || (ov == myv && oj < myj)) { myv = ov; myj = oj; }
                }
                if (lane == 0) { S->bval[warp] = myv; S->bidx[warp] = myj; }
            } else if (warp == 4) {
                // ---- part A: first unassigned candidate in sorted order
                int row = i0 - 1;
                unsigned long long ck = S->cand[row][lane];
                int cidx = (int)(ck & 0xffffffffu);
                unsigned m = __ballot_sync(0xffffffffu, S->p_[cidx] == 0);
                if (!m) {
                    const unsigned long long* gr = g_cand + (long long)(b * GG + row) * KCAND;
                    for (int bs = 32; bs < KCAND; bs += 32) {
                        int kk = bs + lane;
                        bool ok = false;
                        if (kk < KCAND) {
                            ck = gr[kk];
                            cidx = (int)(ck & 0xffffffffu);
                            ok = (S->p_[cidx] == 0);
                        }
                        m = __ballot_sync(0xffffffffu, ok);
                        if (m) break;
                    }
                }
                int L = __ffs(m) - 1;
                unsigned long long w = __shfl_sync(0xffffffffu, ck, L);
                if (lane == 0) S->aPacked = w;
            }
            __syncthreads();                     // barB
            if (t == 0) {
                double ui = S->u[S->s_i0];
                unsigned long long ap = S->aPacked;
                unsigned s  = (unsigned)(ap >> 32);
                unsigned bt = (s & 0x80000000u) ? (s ^ 0x80000000u) : ~s;
                double bv = (double)__uint_as_float(bt) - ui;   // fl(row - ui), v=0
                int bj = (int)(ap & 0xffffffffu);
                #pragma unroll
                for (int w2 = 0; w2 < 4; ++w2) {
                    double wv = S->bval[w2]; int wj = S->bidx[w2];
                    if (wv < bv || (wv == bv && wj < bj)) { bv = wv; bj = wj; }
                }
                int nl = S->s_nlist;
                S->s_delta = bv; S->s_dualCnt = nl;      // applied next phase / outer top
                if (S->p_[bj] == 0) {
                    S->p_[bj] = (unsigned short)i;
                    int c = S->s_asgCnt;
                    S->asgColArr[c] = (unsigned short)bj;
                    S->s_gatherSlot = c; S->s_gatherCol = bj;
                    S->s_asgCnt = c + 1;
                    S->s_done = 1;
                } else {
                    S->chainCol[nl] = (unsigned short)bj;
                    S->chainRow[nl] = S->p_[bj];
                    S->s_nlist = nl + 1;
                    S->used_[bj] = 1;
                    S->s_i0 = S->p_[bj];
                }
            }
        }
    }

    for (int j = t; j < QQ; j += 256) {
        int pi = S->p_[j + 1];
        int off = b * QQ + j;
        long long gi = pi > 0 ? (long long)(pi - 1) : 0;
        if (rawMode) ((long long*)outInds)[off] = gi;
        else         ((float*)outInds)[off] = (float)gi;
        outMask[off] = pi > 0 ? 1.0f : 0.0f;
    }
}

// ---------------------------------------------------------------------------
extern "C" void kernel_launch(void* const* d_in, const int* in_sizes, int n_in,
                              void* d_out, int out_size) {
    const float* sem = (const float*)d_in[0];
    const float* cen = (const float*)d_in[1];
    const float* siz = (const float*)d_in[2];
    const float* gio = (const float*)d_in[3];
    const void*  lab = d_in[4];
    const void*  na  = d_in[5];

    int rawMode = (out_size == 2146304) ? 1 : 0;
    void*  outInds;
    float* outMask;
    float* outCost;
    if (rawMode) {
        outInds = d_out;
        outMask = (float*)((char*)d_out + (size_t)BB * QQ * 8);
        outCost = (float*)((char*)d_out + (size_t)BB * QQ * 8 + (size_t)BB * QQ * 4);
    } else {
        outInds = d_out;
        outMask = (float*)d_out + BB * QQ;
        outCost = (float*)d_out + 2 * BB * QQ;
    }

    // idempotent; first (uncaptured) call sets it
    cudaFuncSetAttribute(lsa_kernel, cudaFuncAttributeMaxDynamicSharedMemorySize,
                         (int)sizeof(LsaSmem));

    prep_kernel<<<1, 1024>>>(lab, na);
    cost_kernel<<<(BB * QQ * GG) / (256 * 4), 256>>>(sem, cen, siz, gio, outCost);
    transpose_kernel<<<dim3(QQ / 32, GG / 32, BB), dim3(32, 8)>>>(outCost);
    sort_kernel<<<BB * GG, 256>>>();
    lsa_kernel<<<BB, 256, sizeof(LsaSmem)>>>(outInds, outMask, outCost, rawMode);
}

// round 5
// speedup vs baseline: 5.0974x; 2.3787x over previous
#include <cuda_runtime.h>
#include <cuda_bf16.h>

#define BB 8
#define QQ 2048
#define GG 128
#define CC 512
#define KCAND 144
#define LSA_THREADS 160

// ---------------- global scratch ----------------
__device__ float g_costT[BB * GG * QQ];                    // [b][g][q]
__device__ unsigned long long g_cand[BB * GG * KCAND];     // sorted (val,idx) per row
__device__ int g_lab[BB * GG];
__device__ int g_n[BB];

// ---------------------------------------------------------------------------
// Detect int64 vs int32 labels/nactual; convert to int32 scratch.
// ---------------------------------------------------------------------------
__global__ void prep_kernel(const void* __restrict__ lab, const void* __restrict__ na) {
    __shared__ int s_bad;
    int t = threadIdx.x;
    if (t == 0) s_bad = 0;
    __syncthreads();
    if (t < 512) {
        long long v = ((const long long*)lab)[t];
        if (v < 0 || v >= CC) s_bad = 1;   // benign race, same value
    }
    __syncthreads();
    if (s_bad == 0) {
        if (t < BB * GG) g_lab[t] = (int)((const long long*)lab)[t];
        if (t < BB)      g_n[t]   = (int)((const long long*)na)[t];
    } else {
        if (t < BB * GG) g_lab[t] = ((const int*)lab)[t];
        if (t < BB)      g_n[t]   = ((const int*)na)[t];
    }
}

// ---------------------------------------------------------------------------
__global__ void cost_kernel(const float* __restrict__ sem,
                            const float* __restrict__ cen,
                            const float* __restrict__ siz,
                            const float* __restrict__ gio,
                            float* __restrict__ outCost) {
    int tid  = blockIdx.x * blockDim.x + threadIdx.x;
    int base = tid << 2;
    if (base >= BB * QQ * GG) return;
    int g  = base & (GG - 1);
    int bq = base >> 7;
    int b  = bq >> 11;

    float4 c4 = *(const float4*)(cen + base);
    float4 s4 = *(const float4*)(siz + base);
    float4 i4 = *(const float4*)(gio + base);
    const float* semRow = sem + ((long long)bq << 9);

    float cls[4];
    #pragma unroll
    for (int k = 0; k < 4; ++k) {
        int lb = g_lab[(b << 7) + g + k] & (CC - 1);
        float x = __ldg(semRow + lb);
        float p = 1.0f / (1.0f + expf(-x));
        float om = 1.0f - p;
        float pos = 0.25f * om * om * (-logf(p + 1e-8f));
        float neg = 0.75f * p * p * (-log1pf(-(p - 1e-8f)));
        cls[k] = pos - neg;
    }
    float4 o;
    o.x = 2.0f * cls[0] + 5.0f * c4.x + s4.x - 2.0f * i4.x;
    o.y = 2.0f * cls[1] + 5.0f * c4.y + s4.y - 2.0f * i4.y;
    o.z = 2.0f * cls[2] + 5.0f * c4.z + s4.z - 2.0f * i4.z;
    o.w = 2.0f * cls[3] + 5.0f * c4.w + s4.w - 2.0f * i4.w;
    *(float4*)(outCost + base) = o;
}

// ---------------------------------------------------------------------------
__global__ void transpose_kernel(const float* __restrict__ src) {
    __shared__ float tile[32][33];
    int b  = blockIdx.z;
    int q0 = blockIdx.x * 32;
    int g0 = blockIdx.y * 32;
    const float* s = src + (long long)b * QQ * GG;
    float* d = g_costT + (long long)b * QQ * GG;
    #pragma unroll
    for (int r = threadIdx.y; r < 32; r += 8)
        tile[r][threadIdx.x] = s[(q0 + r) * GG + g0 + threadIdx.x];
    __syncthreads();
    #pragma unroll
    for (int r = threadIdx.y; r < 32; r += 8)
        d[(g0 + r) * QQ + q0 + threadIdx.x] = tile[threadIdx.x][r];
}

// ---------------------------------------------------------------------------
// Top-K select: exact radix-descent threshold over distinct u64 keys covering
// [KCAND,256] smallest, compact, 256-wide bitonic sort. Rows g>=n[b] skipped.
// ---------------------------------------------------------------------------
__global__ void select_kernel() {
    int rowid = blockIdx.x;                  // b*GG + g
    int b = rowid >> 7, g = rowid & (GG - 1);
    int nb = g_n[b]; if (nb > GG) nb = GG;
    if (g >= nb) return;

    __shared__ unsigned int hist[256];
    __shared__ unsigned long long list[256];
    __shared__ unsigned long long s_boundary;
    __shared__ int s_pivot, s_cumIncl, s_cnt, s_countBelow;

    int t = threadIdx.x;
    const float* row = g_costT + (long long)rowid * QQ;
    unsigned long long k8[8];
    #pragma unroll
    for (int e = 0; e < 8; ++e) {
        int j = t + (e << 8);
        unsigned bits = __float_as_uint(row[j]);
        unsigned s = (bits & 0x80000000u) ? ~bits : (bits | 0x80000000u);
        k8[e] = ((unsigned long long)s << 32) | (unsigned)(j + 1);
    }
    if (t == 0) { s_countBelow = 0; s_cnt = 0; }
    unsigned long long prefix = 0;
    int shift = 56;
    __syncthreads();

    for (int level = 0; level < 8; ++level) {
        hist[t] = 0;
        __syncthreads();
        if (level == 0) {
            #pragma unroll
            for (int e = 0; e < 8; ++e) atomicAdd(&hist[(unsigned)(k8[e] >> 56)], 1u);
        } else {
            unsigned long long am = ~(((unsigned long long)1 << (shift + 8)) - 1);
            #pragma unroll
            for (int e = 0; e < 8; ++e)
                if ((k8[e] & am) == prefix)
                    atomicAdd(&hist[(unsigned)((k8[e] >> shift) & 255)], 1u);
        }
        __syncthreads();
        if (t < 32) {
            int c[8]; int s = 0;
            #pragma unroll
            for (int q = 0; q < 8; ++q) { c[q] = hist[t * 8 + q]; s += c[q]; }
            int incl = s;
            #pragma unroll
            for (int off = 1; off < 32; off <<= 1) {
                int o = __shfl_up_sync(0xffffffffu, incl, off);
                if (t >= off) incl += o;
            }
            int need = KCAND - s_countBelow;
            unsigned msk = __ballot_sync(0xffffffffu, incl >= need);
            int L = __ffs(msk) - 1;
            if (t == L) {
                int running = incl - s; int q;
                #pragma unroll
                for (q = 0; q < 8; ++q) { running += c[q]; if (running >= need) break; }
                s_pivot = t * 8 + q;
                s_cumIncl = running;
            }
        }
        __syncthreads();
        int pivot = s_pivot;
        int keep = s_countBelow + s_cumIncl;
        if (keep <= 256) {
            if (t == 0) {
                unsigned long long bnd = prefix + (((unsigned long long)(pivot + 1)) << shift);
                s_boundary = (bnd == 0) ? 0xFFFFFFFFFFFFFFFFULL : bnd;
            }
            __syncthreads();
            break;
        }
        if (t == 0) s_countBelow = keep - (int)hist[pivot];
        prefix |= ((unsigned long long)pivot) << shift;
        shift -= 8;
        __syncthreads();
    }

    unsigned long long bnd = s_boundary;
    int cnt = 0;
    #pragma unroll
    for (int e = 0; e < 8; ++e) cnt += (k8[e] < bnd) ? 1 : 0;
    int off = atomicAdd(&s_cnt, cnt);
    #pragma unroll
    for (int e = 0; e < 8; ++e)
        if (k8[e] < bnd) list[off++] = k8[e];
    __syncthreads();
    int K = s_cnt;
    if (t >= K) list[t] = 0xFFFFFFFFFFFFFFFFULL;
    __syncthreads();

    unsigned long long key = list[t];
    for (int k = 2; k <= 256; k <<= 1) {
        for (int j = k >> 1; j > 0; j >>= 1) {
            unsigned long long other;
            if (j >= 32) {
                list[t] = key; __syncthreads();
                other = list[t ^ j]; __syncthreads();
            } else {
                other = __shfl_xor_sync(0xffffffffu, key, j);
            }
            bool takeMin = (((t & j) == 0) == ((t & k) == 0));
            if (takeMin ? (other < key) : (other > key)) key = other;
        }
    }
    if (t < KCAND) g_cand[(long long)rowid * KCAND + t] = key;
}

// ---------------------------------------------------------------------------
__device__ __forceinline__ unsigned long long dsort(double x) {
    long long sb = __double_as_longlong(x);
    unsigned long long ub = (unsigned long long)sb;
    return (sb < 0) ? ~ub : (ub | 0x8000000000000000ULL);
}
__device__ __forceinline__ double dunsort(unsigned long long s) {
    unsigned long long ub = (s & 0x8000000000000000ULL) ? (s & 0x7FFFFFFFFFFFFFFFULL) : ~s;
    return __longlong_as_double((long long)ub);
}

struct LsaSmem {
    double u[GG + 2];
    unsigned long long bkey[2][4];
    unsigned long long aPacked[2];
    int bidx[2][4];
    unsigned long long cand[GG][32];
    float asgVals[GG][GG + 1];       // [slot][row], stride 129 conflict-free
    unsigned short p_[QQ + 1];
};

// One barrier per inner iteration; merge redundant on all threads.
// partB (t<128): one lane per assigned column, v/excl/acc in registers.
// partA (warp 4): first unassigned candidate in presorted order.
__global__ void lsa_kernel(void* __restrict__ outInds, float* __restrict__ outMask,
                           const float* __restrict__ outCost, int rawMode) {
    extern __shared__ char smemRaw[];
    LsaSmem* S = (LsaSmem*)smemRaw;
    int b = blockIdx.x, t = threadIdx.x;
    int warp = t >> 5, lane = t & 31;
    int n = g_n[b]; if (n < 0) n = 0; if (n > GG) n = GG;
    const float* costB = outCost + (long long)b * QQ * GG;

    for (int j = t; j <= QQ; j += LSA_THREADS) S->p_[j] = 0;
    for (int j = t; j < GG + 2; j += LSA_THREADS) S->u[j] = 0.0;
    for (int idx = t; idx < GG * 32; idx += LSA_THREADS) {
        int r = idx >> 5, k = idx & 31;
        S->cand[r][k] = g_cand[(long long)(b * GG + r) * KCAND + k];
    }
    __syncthreads();

    double rowAcc = 0.0, myAcc = 0.0, myV = 0.0, curUi = 0.0;
    int myCol = -1, myRow = 0;
    bool myActive = false, myExcl = false, myFresh = false;
    float pendVal = 0.0f; int pendSlot = -1;
    int i = 1, i0 = 1, asgCnt = 0, bjLast = -1, par = 0;
    bool fresh = true;

    if (n > 0) {
        for (;;) {
            // ======================= WORK =======================
            curUi = fresh ? 0.0 : S->u[i0];
            if (t < 128) {
                unsigned long long mk = 0xFFFFFFFFFFFFFFFFULL; int mi = 0;
                if (myActive && !myExcl) {
                    float cv = myFresh ? __ldg(costB + (long long)(myCol - 1) * GG + (i0 - 1))
                                       : S->asgVals[t][i0 - 1];
                    double cur = ((double)cv - curUi) - myV;
                    mk = dsort(cur); mi = (myRow << 16) | myCol;
                }
                #pragma unroll
                for (int off = 16; off; off >>= 1) {
                    unsigned long long ok = __shfl_down_sync(0xffffffffu, mk, off);
                    int oi = __shfl_down_sync(0xffffffffu, mi, off);
                    int oc = oi & 0xffff, mc = mi & 0xffff;
                    if (ok < mk || (ok == mk && oc < mc)) { mk = ok; mi = oi; }
                }
                if (lane == 0) { S->bkey[par][warp] = mk; S->bidx[par][warp] = mi; }
                if (pendSlot >= 0) { S->asgVals[pendSlot][t] = pendVal; pendSlot = -1; }
            } else {
                int row = i0 - 1;
                unsigned long long ck = S->cand[row][lane];
                int cidx = (int)(ck & 0xffffffffu);
                bool ok0 = (S->p_[cidx] == 0) && (cidx != bjLast);
                unsigned m = __ballot_sync(0xffffffffu, ok0);
                if (!m) {
                    const unsigned long long* gr = g_cand + (long long)(b * GG + row) * KCAND;
                    for (int bs = 32; bs < KCAND; bs += 32) {
                        int kk = bs + lane;
                        bool okf = false;
                        if (kk < KCAND) {
                            ck = gr[kk];
                            int ci = (int)(ck & 0xffffffffu);
                            okf = (S->p_[ci] == 0) && (ci != bjLast);
                        }
                        m = __ballot_sync(0xffffffffu, okf);
                        if (m) break;
                    }
                }
                int L = __ffs(m) - 1;
                if (L < 0) L = 0;     // unreachable: <=129 blocked < KCAND
                unsigned long long w = __shfl_sync(0xffffffffu, ck, L);
                if (lane == 0) S->aPacked[par] = w;
            }
            __syncthreads();
            // ======================= MERGE (redundant) =======================
            bool wasFresh = myFresh;
            unsigned long long ak = S->aPacked[par];
            unsigned sf = (unsigned)(ak >> 32);
            unsigned fb = (sf & 0x80000000u) ? (sf & 0x7FFFFFFFu) : ~sf;
            double av = (double)__uint_as_float(fb) - curUi;   // v==0 on unassigned
            unsigned long long bk = dsort(av);
            int bcol = (int)(ak & 0xffffffffu);
            int brow = 0;                                      // 0 => from partA
            #pragma unroll
            for (int w2 = 0; w2 < 4; ++w2) {
                unsigned long long wk = S->bkey[par][w2]; int wi = S->bidx[par][w2];
                int wc = wi & 0xffff;
                if (wk < bk || (wk == bk && wc < bcol)) { bk = wk; bcol = wc; brow = wi >> 16; }
            }
            par ^= 1;
            double delta = dunsort(bk);
            rowAcc += delta;
            if (myExcl) myAcc += delta;
            if (brow == 0) {
                // done: bcol unassigned -> assign to row i; flush duals
                if (myExcl) { myV -= myAcc; S->u[myRow] += myAcc; myExcl = false; myAcc = 0.0; }
                if (t == 0) { S->p_[bcol] = (unsigned short)i; S->u[i] += rowAcc; }
                if (t == asgCnt) {
                    myActive = true; myCol = bcol; myRow = i;
                    myV = 0.0; myAcc = 0.0; myExcl = false; myFresh = true;
                }
                if (t < GG) {
                    pendVal = __ldg(costB + (long long)(bcol - 1) * GG + t);
                    pendSlot = asgCnt;
                }
                asgCnt++; bjLast = bcol; i++; rowAcc = 0.0;
                if (i > n) break;
                i0 = i; fresh = true;
            } else {
                if (myActive && myCol == bcol) { myExcl = true; myAcc = 0.0; }
                i0 = brow; fresh = false; bjLast = -1;
            }
            if (wasFresh) myFresh = false;
        }
    }
    __syncthreads();

    for (int j = t; j < QQ; j += LSA_THREADS) {
        int pi = S->p_[j + 1];
        int off = b * QQ + j;
        long long gi = pi > 0 ? (long long)(pi - 1) : 0;
        if (rawMode) ((long long*)outInds)[off] = gi;
        else         ((float*)outInds)[off] = (float)gi;
        outMask[off] = pi > 0 ? 1.0f : 0.0f;
    }
}

// ---------------------------------------------------------------------------
extern "C" void kernel_launch(void* const* d_in, const int* in_sizes, int n_in,
                              void* d_out, int out_size) {
    const float* sem = (const float*)d_in[0];
    const float* cen = (const float*)d_in[1];
    const float* siz = (const float*)d_in[2];
    const float* gio = (const float*)d_in[3];
    const void*  lab = d_in[4];
    const void*  na  = d_in[5];

    int rawMode = (out_size == 2146304) ? 1 : 0;
    void*  outInds;
    float* outMask;
    float* outCost;
    if (rawMode) {
        outInds = d_out;
        outMask = (float*)((char*)d_out + (size_t)BB * QQ * 8);
        outCost = (float*)((char*)d_out + (size_t)BB * QQ * 8 + (size_t)BB * QQ * 4);
    } else {
        outInds = d_out;
        outMask = (float*)d_out + BB * QQ;
        outCost = (float*)d_out + 2 * BB * QQ;
    }

    cudaFuncSetAttribute(lsa_kernel, cudaFuncAttributeMaxDynamicSharedMemorySize,
                         (int)sizeof(LsaSmem));

    prep_kernel<<<1, 1024>>>(lab, na);
    cost_kernel<<<(BB * QQ * GG) / (256 * 4), 256>>>(sem, cen, siz, gio, outCost);
    transpose_kernel<<<dim3(QQ / 32, GG / 32, BB), dim3(32, 8)>>>(outCost);
    select_kernel<<<BB * GG, 256>>>();
    lsa_kernel<<<BB, LSA_THREADS, sizeof(LsaSmem)>>>(outInds, outMask, outCost, rawMode);
}